// round 17
// baseline (speedup 1.0000x reference)
#include <cuda_runtime.h>
#include <cuda_bf16.h>

#define NN       8192
#define EE       262144
#define IN_NODE  11
#define H_NF     4
#define OUT_NF   4
#define EMB_NF   2

#define COL_BLKS 8                             // column chunks per row (1024 cols each)
#define ROW_BLKS (NN / 2)                      // 4096 row-pairs
#define DEC_TOT  (COL_BLKS * ROW_BLKS)         // 32768 decode blocks
#define COLS_PER_BLK (NN / COL_BLKS)           // 1024 columns

#define SCAT_BLK 256                           // 256 blocks x 256 thr x 4 edges
#define INIT_BLK 8                             // 8 blocks x 256 thr x 4 nodes

// Scratch (static device globals — zero-initialized at module load;
// k_decode restores g_emb = 0 at the end of every call, so k_fused always
// observes zeros on entry, including across graph replays).
__device__ __align__(16) float g_emb[NN * EMB_NF];
__device__ int g_fin;

// ---------------------------------------------------------------------------
// Fold helper: T = W2 @ We  (4x2). ~32 FMA; computed locally where needed.
// ---------------------------------------------------------------------------
__device__ __forceinline__ void fold_T(const float* __restrict__ W2,
                                       const float* __restrict__ We,
                                       float T[H_NF][EMB_NF]) {
#pragma unroll
    for (int h = 0; h < H_NF; h++)
#pragma unroll
        for (int j = 0; j < EMB_NF; j++) {
            float s = 0.0f;
#pragma unroll
            for (int o = 0; o < OUT_NF; o++)
                s = fmaf(__ldg(&W2[h * OUT_NF + o]), __ldg(&We[o * EMB_NF + j]), s);
            T[h][j] = s;
        }
}

// ---------------------------------------------------------------------------
// k1 (fused): blocks [0, SCAT_BLK) scatter 4 edges/thread,
//             blocks [SCAT_BLK, SCAT_BLK+INIT_BLK) add base emb, 4 nodes/thread.
// Scatter batches its global loads up front (MLP=8), then 4 float2 atomics.
// Each block fences + fires the PDL trigger when its adds are visible.
// ---------------------------------------------------------------------------
__global__ void __launch_bounds__(256) k_fused(
        const int* __restrict__ eidx, const float* __restrict__ eattr,
        const float* __restrict__ nf,
        const float* __restrict__ W1, const float* __restrict__ b1,
        const float* __restrict__ W2, const float* __restrict__ b2,
        const float* __restrict__ We, const float* __restrict__ be) {
    int b = blockIdx.x;

    if (b < SCAT_BLK) {
        int g = b * 256 + threadIdx.x;           // 65536 threads
        float4 a[4];
        int    r[4];
#pragma unroll
        for (int k4 = 0; k4 < 4; k4++) {
            int e = g + k4 * 65536;
            a[k4] = __ldg(reinterpret_cast<const float4*>(&eattr[e * 4]));
            r[k4] = __ldg(&eidx[e]);
        }
        float T[H_NF][EMB_NF];
        fold_T(W2, We, T);
        float P[4][2];
#pragma unroll
        for (int k = 0; k < 4; k++)
#pragma unroll
            for (int j = 0; j < 2; j++) {
                float s = 0.0f;
#pragma unroll
                for (int h = 0; h < H_NF; h++)
                    s = fmaf(__ldg(&W1[(IN_NODE + k) * H_NF + h]), T[h][j], s);
                P[k][j] = s;
            }
#pragma unroll
        for (int k4 = 0; k4 < 4; k4++) {
            float c0 = a[k4].x * P[0][0];
            float c1 = a[k4].x * P[0][1];
            c0 = fmaf(a[k4].y, P[1][0], c0); c1 = fmaf(a[k4].y, P[1][1], c1);
            c0 = fmaf(a[k4].z, P[2][0], c0); c1 = fmaf(a[k4].z, P[2][1], c1);
            c0 = fmaf(a[k4].w, P[3][0], c0); c1 = fmaf(a[k4].w, P[3][1], c1);
            atomicAdd(reinterpret_cast<float2*>(&g_emb[r[k4] * 2]),
                      make_float2(c0, c1));
        }
    } else {
        float T[H_NF][EMB_NF];
        fold_T(W2, We, T);
        float cb0 = __ldg(&be[0]), cb1 = __ldg(&be[1]);
#pragma unroll
        for (int h = 0; h < H_NF; h++) {
            float bh = __ldg(&b1[h]);
            cb0 = fmaf(bh, T[h][0], cb0);
            cb1 = fmaf(bh, T[h][1], cb1);
        }
#pragma unroll
        for (int o = 0; o < OUT_NF; o++) {
            float bo = __ldg(&b2[o]);
            cb0 = fmaf(bo, __ldg(&We[o * EMB_NF + 0]), cb0);
            cb1 = fmaf(bo, __ldg(&We[o * EMB_NF + 1]), cb1);
        }
        float M[IN_NODE][2];
#pragma unroll
        for (int k = 0; k < IN_NODE; k++)
#pragma unroll
            for (int j = 0; j < 2; j++) {
                float s = 0.0f;
#pragma unroll
                for (int h = 0; h < H_NF; h++)
                    s = fmaf(__ldg(&W1[k * H_NF + h]), T[h][j], s);
                M[k][j] = s;
            }
        int g = (b - SCAT_BLK) * 256 + threadIdx.x;   // 2048 threads
#pragma unroll
        for (int k4 = 0; k4 < 4; k4++) {
            int i = g + k4 * 2048;
            float c0 = cb0, c1 = cb1;
#pragma unroll
            for (int k = 0; k < IN_NODE; k++) {
                float x = __ldg(&nf[i * IN_NODE + k]);
                c0 = fmaf(x, M[k][0], c0);
                c1 = fmaf(x, M[k][1], c1);
            }
            atomicAdd(reinterpret_cast<float2*>(&g_emb[i * 2]),
                      make_float2(c0, c1));
        }
    }

    __threadfence();
    cudaTriggerProgrammaticLaunchCompletion();
}

// ---------------------------------------------------------------------------
// k2: dense decode with COLUMN-MAJOR block tiling for concurrent-write
// density. Grid (COL_BLKS=8, ROW_BLKS=4096); block (bx, by) writes columns
// [bx*1024, bx*1024+1024) of rows 2by and 2by+1. CUDA dispatches x-fastest,
// so the ~888 concurrently-resident blocks cover ~111 COMPLETE row-pairs —
// a dense ~7MB write footprint instead of 888 scattered 64KB streams across
// 57MB. Stores remain perfectly 128B-coalesced per warp.
// Blocks with by<2 emit the node_emb tail. Last finishing block re-zeros
// g_emb (all reads complete) to restore k_fused's invariant.
// ---------------------------------------------------------------------------
__device__ __forceinline__ float sig_pair(float2 ei, float ex, float ey) {
    float dx = ei.x - ex;
    float dy = ei.y - ey;
    float d  = fmaf(dx, dx, dy * dy);
    float t  = fmaf(10.0f, d, -1.0f);
    return __fdividef(1.0f, 1.0f + __expf(-t));
}

__global__ void __launch_bounds__(256) k_decode(float* __restrict__ out,
                                                float* __restrict__ out_emb) {
    __shared__ int s_last;
    int bx = blockIdx.x;               // 0..7  column chunk
    int by = blockIdx.y;               // 0..4095 row pair
    int i0 = by * 2;

    // Wait for k_fused (no-op if launched without the PDL attribute).
    cudaGridDependencySynchronize();

    // node_emb tail: 16 blocks (by<2, all bx) x 256 thr x 1 float4
    if (by < 2) {
        int t = (by * COL_BLKS + bx) * 256 + threadIdx.x;   // 0..4095
        reinterpret_cast<float4*>(out_emb)[t] =
            reinterpret_cast<const float4*>(g_emb)[t];
    }

    float2 e0 = *reinterpret_cast<const float2*>(&g_emb[i0 * 2]);
    float2 e1 = *reinterpret_cast<const float2*>(&g_emb[(i0 + 1) * 2]);

    int jb = bx * COLS_PER_BLK + threadIdx.x * 4;           // this thread's 4 cols
    float4 ja = *reinterpret_cast<const float4*>(&g_emb[jb * 2]);      // j,j+1
    float4 jc = *reinterpret_cast<const float4*>(&g_emb[jb * 2 + 4]);  // j+2,j+3

    float4 r0, r1;
    r0.x = sig_pair(e0, ja.x, ja.y);  r1.x = sig_pair(e1, ja.x, ja.y);
    r0.y = sig_pair(e0, ja.z, ja.w);  r1.y = sig_pair(e1, ja.z, ja.w);
    r0.z = sig_pair(e0, jc.x, jc.y);  r1.z = sig_pair(e1, jc.x, jc.y);
    r0.w = sig_pair(e0, jc.z, jc.w);  r1.w = sig_pair(e1, jc.z, jc.w);

    unsigned k0 = (unsigned)i0 - (unsigned)jb;              // diag row i0
    if (k0 < 4u) {
        if (k0 == 0u)      r0.x = 0.0f;
        else if (k0 == 1u) r0.y = 0.0f;
        else if (k0 == 2u) r0.z = 0.0f;
        else               r0.w = 0.0f;
    }
    unsigned k1 = (unsigned)(i0 + 1) - (unsigned)jb;        // diag row i0+1
    if (k1 < 4u) {
        if (k1 == 0u)      r1.x = 0.0f;
        else if (k1 == 1u) r1.y = 0.0f;
        else if (k1 == 2u) r1.z = 0.0f;
        else               r1.w = 0.0f;
    }

    __stcs(reinterpret_cast<float4*>(&out[(size_t)i0 * NN + jb]), r0);
    __stcs(reinterpret_cast<float4*>(&out[(size_t)(i0 + 1) * NN + jb]), r1);

    // ---- epilogue: last finishing block restores g_emb = 0, g_fin = 0 ----
    __syncthreads();
    if (threadIdx.x == 0) {
        __threadfence();
        s_last = (atomicAdd(&g_fin, 1) == DEC_TOT - 1) ? 1 : 0;
    }
    __syncthreads();
    if (s_last) {
        float4 z = make_float4(0.f, 0.f, 0.f, 0.f);
#pragma unroll
        for (int p = 0; p < NN * EMB_NF / 4 / 256; p++)     // 16 float4/thread
            reinterpret_cast<float4*>(g_emb)[p * 256 + threadIdx.x] = z;
        if (threadIdx.x == 0) g_fin = 0;
    }
}

// ---------------------------------------------------------------------------
// launch
// ---------------------------------------------------------------------------
extern "C" void kernel_launch(void* const* d_in, const int* in_sizes, int n_in,
                              void* d_out, int out_size) {
    const float* node_feats = (const float*)d_in[0];
    const int*   edge_index = (const int*)d_in[1];
    const float* edge_attr  = (const float*)d_in[2];
    const float* W1 = (const float*)d_in[3];
    const float* b1 = (const float*)d_in[4];
    const float* W2 = (const float*)d_in[5];
    const float* b2 = (const float*)d_in[6];
    const float* We = (const float*)d_in[7];
    const float* be = (const float*)d_in[8];

    float* out = (float*)d_out;
    float* out_emb = out + (size_t)NN * NN;   // adj [N*N] then node_emb [N*2]

    k_fused<<<SCAT_BLK + INIT_BLK, 256>>>(edge_index, edge_attr, node_feats,
                                          W1, b1, W2, b2, We, be);

    // k_decode with programmatic dependent launch (overlap launch ramp with
    // k_fused). Fall back to a plain launch if the attribute is rejected.
    cudaLaunchAttribute attrs[1];
    attrs[0].id = cudaLaunchAttributeProgrammaticStreamSerialization;
    attrs[0].val.programmaticStreamSerializationAllowed = 1;
    cudaLaunchConfig_t cfg = {};
    cfg.gridDim  = dim3(COL_BLKS, ROW_BLKS, 1);
    cfg.blockDim = dim3(256, 1, 1);
    cfg.dynamicSmemBytes = 0;
    cfg.attrs    = attrs;
    cfg.numAttrs = 1;
    cudaError_t err = cudaLaunchKernelEx(&cfg, k_decode, out, out_emb);
    if (err != cudaSuccess) {
        (void)cudaGetLastError();   // clear sticky error, fall back
        k_decode<<<dim3(COL_BLKS, ROW_BLKS, 1), 256>>>(out, out_emb);
    }
}